// round 1
// baseline (speedup 1.0000x reference)
#include <cuda_runtime.h>
#include <cstdint>
#include <cstddef>

#define T_DIM 2048
#define B_DIM 32
#define E_DIM 512
#define N_DIM 512
#define K_DIM 512
#define M_DIM (T_DIM * B_DIM)   // 65536 rows, row m = t*B + b

// ---------------- device scratch (static: no allocations allowed) ----------
__device__ float g_w[M_DIM];              // weight[t*B + b] (unmasked sigmoid)
__device__ int   g_len[B_DIM];            // valid length per batch
__device__ int   g_nrows[B_DIM];          // number of output (fired/tail) rows
__device__ int   g_rt0[B_DIM * T_DIM];    // per-row segment start t
__device__ int   g_rt1[B_DIM * T_DIM];    // per-row segment end t
__device__ float g_rc0[B_DIM * T_DIM];    // coefficient at t0
__device__ float g_rc1[B_DIM * T_DIM];    // coefficient at t1
__device__ float g_rmult[B_DIM * T_DIM];  // row multiplier (1 or tail scale)

// ---------------- K0: mask dtype detection + per-batch lengths --------------
// padding_mask is bool in the reference; the harness may hand it to us as
// int32 (0/1), float32 (0.0/1.0) or uint8/bool (0/1). Mask rows are a zero
// prefix followed by a ones suffix (pad is a suffix), rows are 2048 elements
// (dword aligned), so the first 16384 dwords (safe under every interpretation)
// classify unambiguously:
//   int32  -> dwords in {0, 1}
//   float32-> dwords in {0, 0x3F800000}
//   uint8  -> packed transition/all-one dwords (0x01010101, 0x01010000, ...)
__global__ void k0_mask(const void* __restrict__ mask) {
    __shared__ int flags[3];  // [0]=int32, [1]=float32, [2]=uint8
    int tid = threadIdx.x;
    if (tid < 3) flags[tid] = 0;
    __syncthreads();
    const unsigned* dw = (const unsigned*)mask;
    for (int i = tid; i < 16384; i += blockDim.x) {
        unsigned d = dw[i];
        if (d != 0u) {
            if (d == 1u)                flags[0] = 1;
            else if (d == 0x3F800000u)  flags[1] = 1;
            else                        flags[2] = 1;
        }
    }
    __syncthreads();
    int kind = flags[2] ? 2 : (flags[1] ? 1 : 0);

    // warp w counts zeros (== non-pad) in batch row w
    int warp = tid >> 5, lane = tid & 31;
    int cnt = 0;
    if (kind == 2) {
        const unsigned char* p = (const unsigned char*)mask + warp * T_DIM;
        for (int t = lane; t < T_DIM; t += 32) cnt += (p[t] == 0);
    } else {
        const unsigned* p = dw + (size_t)warp * T_DIM;
        for (int t = lane; t < T_DIM; t += 32) cnt += (p[t] == 0u);
    }
    for (int o = 16; o > 0; o >>= 1) cnt += __shfl_down_sync(0xffffffffu, cnt, o);
    if (lane == 0) g_len[warp] = cnt;
}

// ---------------- K1: fused fp32 GEMM + ReLU + projection + sigmoid ---------
// weight[m] = sigmoid( sum_n relu( sum_k A[m,k]*W1[k,n] + b1[n] ) * w2[n] + b2 )
// Block tile: 128 rows x 128 cols, looped over 4 col-tiles (full N in-block so
// the row reduction stays deterministic, no atomics). Double-buffered smem.
#define BMT 128
#define BNT 128
#define BKT 16
#define KTILES (K_DIM / BKT)   // 32
#define AS_STR (BMT + 4)       // pad to kill transpose-store bank conflicts

__global__ __launch_bounds__(256, 2) void k1_gemm(
    const float* __restrict__ A,   // [M][K] row-major (enc, m = t*B+b)
    const float* __restrict__ W1,  // [K][N] row-major
    const float* __restrict__ b1,  // [N]
    const float* __restrict__ w2,  // [N]
    const float* __restrict__ b2)  // [1]
{
    __shared__ float As[2][BKT][AS_STR];
    __shared__ float Bs[2][BKT][BNT];
    __shared__ float red[BMT][17];

    const int tid = threadIdx.x;
    const int tx = tid & 15, ty = tid >> 4;
    const int m0 = blockIdx.x * BMT;

    // A loads: 512 float4 per k-tile, 2 per thread
    const int aRow0 = tid >> 2;            // 0..63
    const int aRow1 = aRow0 + 64;          // 64..127
    const int aCol  = (tid & 3) * 4;       // 0,4,8,12
    // B loads: 512 float4 per k-tile, 2 per thread
    const int bRow0 = tid >> 5;            // 0..7
    const int bRow1 = bRow0 + 8;           // 8..15
    const int bCol  = (tid & 31) * 4;      // 0..124

    float rowacc[8];
#pragma unroll
    for (int i = 0; i < 8; i++) rowacc[i] = 0.f;
    const float b2s = b2[0];

    for (int n0 = 0; n0 < N_DIM; n0 += BNT) {
        float acc[8][8];
#pragma unroll
        for (int i = 0; i < 8; i++)
#pragma unroll
            for (int j = 0; j < 8; j++) acc[i][j] = 0.f;

        float4 aR0, aR1, bR0, bR1;
        // prologue: tile 0 -> buf 0
        aR0 = *(const float4*)(A + (size_t)(m0 + aRow0) * K_DIM + aCol);
        aR1 = *(const float4*)(A + (size_t)(m0 + aRow1) * K_DIM + aCol);
        bR0 = *(const float4*)(W1 + (size_t)bRow0 * N_DIM + n0 + bCol);
        bR1 = *(const float4*)(W1 + (size_t)bRow1 * N_DIM + n0 + bCol);
        As[0][aCol + 0][aRow0] = aR0.x; As[0][aCol + 1][aRow0] = aR0.y;
        As[0][aCol + 2][aRow0] = aR0.z; As[0][aCol + 3][aRow0] = aR0.w;
        As[0][aCol + 0][aRow1] = aR1.x; As[0][aCol + 1][aRow1] = aR1.y;
        As[0][aCol + 2][aRow1] = aR1.z; As[0][aCol + 3][aRow1] = aR1.w;
        *(float4*)&Bs[0][bRow0][bCol] = bR0;
        *(float4*)&Bs[0][bRow1][bCol] = bR1;
        __syncthreads();

        for (int kt = 0; kt < KTILES; kt++) {
            const int cur = kt & 1;
            if (kt + 1 < KTILES) {
                const int kb = (kt + 1) * BKT;
                aR0 = *(const float4*)(A + (size_t)(m0 + aRow0) * K_DIM + kb + aCol);
                aR1 = *(const float4*)(A + (size_t)(m0 + aRow1) * K_DIM + kb + aCol);
                bR0 = *(const float4*)(W1 + (size_t)(kb + bRow0) * N_DIM + n0 + bCol);
                bR1 = *(const float4*)(W1 + (size_t)(kb + bRow1) * N_DIM + n0 + bCol);
            }
#pragma unroll
            for (int kk = 0; kk < BKT; kk++) {
                float4 a0 = *(const float4*)&As[cur][kk][ty * 8];
                float4 a1 = *(const float4*)&As[cur][kk][ty * 8 + 4];
                float4 c0 = *(const float4*)&Bs[cur][kk][tx * 8];
                float4 c1 = *(const float4*)&Bs[cur][kk][tx * 8 + 4];
                float av[8] = {a0.x, a0.y, a0.z, a0.w, a1.x, a1.y, a1.z, a1.w};
                float bv[8] = {c0.x, c0.y, c0.z, c0.w, c1.x, c1.y, c1.z, c1.w};
#pragma unroll
                for (int i = 0; i < 8; i++)
#pragma unroll
                    for (int j = 0; j < 8; j++)
                        acc[i][j] = fmaf(av[i], bv[j], acc[i][j]);
            }
            if (kt + 1 < KTILES) {
                const int nb = cur ^ 1;
                As[nb][aCol + 0][aRow0] = aR0.x; As[nb][aCol + 1][aRow0] = aR0.y;
                As[nb][aCol + 2][aRow0] = aR0.z; As[nb][aCol + 3][aRow0] = aR0.w;
                As[nb][aCol + 0][aRow1] = aR1.x; As[nb][aCol + 1][aRow1] = aR1.y;
                As[nb][aCol + 2][aRow1] = aR1.z; As[nb][aCol + 3][aRow1] = aR1.w;
                *(float4*)&Bs[nb][bRow0][bCol] = bR0;
                *(float4*)&Bs[nb][bRow1][bCol] = bR1;
                __syncthreads();
            }
        }

        // fused epilogue for this n-tile: relu(h + b1) * w2 -> row partials
        float b1r[8], w2r[8];
#pragma unroll
        for (int j = 0; j < 8; j++) {
            b1r[j] = b1[n0 + tx * 8 + j];
            w2r[j] = w2[n0 + tx * 8 + j];
        }
#pragma unroll
        for (int i = 0; i < 8; i++)
#pragma unroll
            for (int j = 0; j < 8; j++) {
                float h = fmaxf(acc[i][j] + b1r[j], 0.f);
                rowacc[i] = fmaf(h, w2r[j], rowacc[i]);
            }
        __syncthreads();  // before next n-tile's prologue reuses buf 0
    }

    // reduce rowacc across the 16 tx threads of each row (fixed order)
#pragma unroll
    for (int i = 0; i < 8; i++) red[ty * 8 + i][tx] = rowacc[i];
    __syncthreads();
    if (tid < BMT) {
        float s = 0.f;
#pragma unroll
        for (int x = 0; x < 16; x++) s += red[tid][x];
        float arg = s + b2s;
        g_w[m0 + tid] = 1.0f / (1.0f + expf(-arg));
    }
}

// ---------------- K2: scalar CIF scan per batch (warp-cooperative) ----------
// Emits per output row: segment [t0,t1], boundary coefficients c0/c1 and a
// multiplier. Interior coefficients are just g_w[t]. Also writes fired_marks
// and quantity_out.
__global__ void k2_scan(float* __restrict__ out_marks,
                        float* __restrict__ out_quantity,
                        int write_extras)
{
    const int b = blockIdx.x;
    const int lane = threadIdx.x;
    const int L = g_len[b];

    float prev_w = 0.f, quantity = 0.f, seg_c0 = 0.f, last_w = 0.f;
    int seg_t0 = 0, r = 0;

    for (int chunk = 0; chunk < T_DIM; chunk += 32) {
        float wv = g_w[(chunk + lane) * B_DIM + b];
        float mymark = 0.f;
#pragma unroll 1
        for (int j = 0; j < 32; j++) {
            const int t = chunk + j;
            float w = __shfl_sync(0xffffffffu, wv, j);
            float mark = 0.f;
            if (t < L) {
                quantity += w;
                if (t == 0) seg_c0 = w;
                bool fired = (prev_w + w >= 1.0f);
                if (fired) {
                    float remained = 1.0f - prev_w;
                    if (lane == 0) {
                        int idx = b * T_DIM + r;
                        g_rt0[idx] = seg_t0; g_rt1[idx] = t;
                        g_rc0[idx] = seg_c0; g_rc1[idx] = remained;
                        g_rmult[idx] = 1.0f;
                    }
                    r++;
                    prev_w = w - remained;
                    seg_t0 = t;
                    seg_c0 = w - remained;
                    mark = 1.f;
                } else {
                    prev_w = w + prev_w;
                }
                last_w = w;
            } else if (t == L) {
                // tail row: cur_w = prev_w (w=0, cannot fire); nonzero iff > 0.6
                if (prev_w > 0.6f) {
                    if (lane == 0) {
                        int idx = b * T_DIM + r;
                        g_rt0[idx] = seg_t0; g_rt1[idx] = L - 1;
                        g_rc0[idx] = seg_c0; g_rc1[idx] = last_w;
                        g_rmult[idx] = 1.0f / (prev_w + 1e-10f);
                    }
                    r++;
                    mark = 1.f;
                }
            }
            if (lane == j) mymark = mark;
        }
        if (write_extras) out_marks[b * T_DIM + chunk + lane] = mymark;
    }
    if (lane == 0) {
        g_nrows[b] = r;
        if (write_extras) out_quantity[b] = quantity;
    }
}

// ---------------- K3: segment sums written directly in compacted order ------
// One block per (output row r, batch b). 128 threads x float4 = 512 elems.
__global__ __launch_bounds__(128) void k3_rows(
    const float* __restrict__ x,       // enc [T][B][E]
    float* __restrict__ out_cif,       // [B][T][E]
    float* __restrict__ out_mask,      // [B][T]
    int write_extras)
{
    const int r = blockIdx.x, b = blockIdx.y;
    const int tid = threadIdx.x;
    const int nr = g_nrows[b];

    float4 acc = make_float4(0.f, 0.f, 0.f, 0.f);
    if (r < nr) {
        const int idx = b * T_DIM + r;
        const int t0 = g_rt0[idx], t1 = g_rt1[idx];
        const float c0 = g_rc0[idx], c1 = g_rc1[idx], mult = g_rmult[idx];
        const float* xb = x + (size_t)b * E_DIM + tid * 4;
        const size_t tstride = (size_t)B_DIM * E_DIM;

        float4 v = *(const float4*)(xb + (size_t)t0 * tstride);
        acc.x = c0 * v.x; acc.y = c0 * v.y; acc.z = c0 * v.z; acc.w = c0 * v.w;
        for (int t = t0 + 1; t < t1; t++) {
            float w = g_w[t * B_DIM + b];
            v = *(const float4*)(xb + (size_t)t * tstride);
            acc.x = fmaf(w, v.x, acc.x); acc.y = fmaf(w, v.y, acc.y);
            acc.z = fmaf(w, v.z, acc.z); acc.w = fmaf(w, v.w, acc.w);
        }
        if (t1 > t0) {
            v = *(const float4*)(xb + (size_t)t1 * tstride);
            acc.x = fmaf(c1, v.x, acc.x); acc.y = fmaf(c1, v.y, acc.y);
            acc.z = fmaf(c1, v.z, acc.z); acc.w = fmaf(c1, v.w, acc.w);
        }
        acc.x *= mult; acc.y *= mult; acc.z *= mult; acc.w *= mult;
    }
    *(float4*)(out_cif + ((size_t)(b * T_DIM + r)) * E_DIM + tid * 4) = acc;
    if (write_extras && tid == 0) out_mask[b * T_DIM + r] = (r < nr) ? 1.f : 0.f;
}

// ---------------- launch ----------------------------------------------------
extern "C" void kernel_launch(void* const* d_in, const int* in_sizes, int n_in,
                              void* d_out, int out_size)
{
    const float* enc = (const float*)d_in[0];
    const void*  mask = d_in[1];
    const float* dense_w = (const float*)d_in[2];
    const float* dense_b = (const float*)d_in[3];
    const float* wproj_w = (const float*)d_in[4];
    const float* wproj_b = (const float*)d_in[5];
    float* out = (float*)d_out;

    const int cif_elems = B_DIM * T_DIM * E_DIM;
    const int full = cif_elems + B_DIM * T_DIM + B_DIM + B_DIM * T_DIM;
    const int extras = (out_size >= full) ? 1 : 0;

    float* out_mask   = out + cif_elems;
    float* out_q      = out_mask + B_DIM * T_DIM;
    float* out_marks  = out_q + B_DIM;

    k0_mask<<<1, 1024>>>(mask);
    k1_gemm<<<M_DIM / BMT, 256>>>(enc, dense_w, dense_b, wproj_w, wproj_b);
    k2_scan<<<B_DIM, 32>>>(out_marks, out_q, extras);
    k3_rows<<<dim3(T_DIM, B_DIM), 128>>>(enc, out, out_mask, extras);
}